// round 14
// baseline (speedup 1.0000x reference)
#include <cuda_runtime.h>
#include <math.h>

#define A_N    76725
#define NCLS   80
#define NB     8
#define NTASK  (NB*NCLS)
#define KPRE   256
#define MDPC   100
#define MAXD   100
#define CCAP   3072
#define BUFN   1024
#define NBIN2  2048
#define NBINF  4096
#define PUSH_T 2.5f
#define CNTSTR 32
#define SEL_BASE 0xBF600000u
#define FIN_BASE 0xBD400000u
#define TILES_PB 4

__device__ unsigned long long g_cand[(size_t)NTASK * CCAP];
__device__ int    g_cnt[NTASK * CNTSTR];        // zero-init; k_select resets after use
__device__ float  g_cls_scores[NTASK * MDPC];
__device__ float4 g_cls_boxes[NTASK * MDPC];

__device__ __forceinline__ unsigned fkey32(float x) {
    unsigned b = __float_as_uint(x);
    return (b & 0x80000000u) ? ~b : (b | 0x80000000u);
}

// legacy barrier-scan (fallback + k_final)
template <int BPT>
__device__ __forceinline__ unsigned suffix_total(const unsigned* hist, unsigned* csum, int tid) {
    unsigned s = 0;
    const int base = tid * BPT;
#pragma unroll
    for (int r = 0; r < BPT; ++r) s += hist[base + r];
    csum[tid] = s;
    __syncthreads();
    for (int off = 1; off < 256; off <<= 1) {
        unsigned add = (tid + off < 256) ? csum[tid + off] : 0u;
        __syncthreads();
        csum[tid] += add;
        __syncthreads();
    }
    return csum[0];
}

template <int BPT>
__device__ __forceinline__ void crossing(const unsigned* hist, const unsigned* csum, int* ctrl,
                                         unsigned target, int tid) {
    unsigned run = (tid + 1 < 256) ? csum[tid + 1] : 0u;
    const int base = tid * BPT;
    for (int i = base + BPT - 1; i >= base; --i) {
        unsigned h = hist[i];
        run += h;
        if (run >= target && run - h < target) { ctrl[0] = i; ctrl[1] = (int)(run - h); }
    }
    __syncthreads();
}

// shuffle-based inclusive suffix over 256 per-thread sums; 2 barriers.
__device__ __forceinline__ unsigned suffix_scan(unsigned s, int tid, volatile unsigned* wtot) {
    unsigned v = s;
    const int lane = tid & 31;
#pragma unroll
    for (int off = 1; off < 32; off <<= 1) {
        unsigned t = __shfl_down_sync(0xFFFFFFFFu, v, off);
        if (lane + off < 32) v += t;
    }
    const int w = tid >> 5;
    if (lane == 0) wtot[w] = v;
    __syncthreads();
    if (tid == 0) {
        unsigned run = 0;
        for (int i = 7; i >= 0; --i) { unsigned t2 = wtot[i]; wtot[i] = run; run += t2; }
        wtot[8] = run;
    }
    __syncthreads();
    return v + wtot[w];
}

__device__ __forceinline__ void crossing2(const unsigned* hist, unsigned runstart, int* ctrl,
                                          unsigned target, int tid) {
    unsigned run = runstart;
    const int base = tid * 8;
#pragma unroll
    for (int i = base + 7; i >= base; --i) {
        unsigned h = hist[i];
        run += h;
        if (run >= target && run - h < target) { ctrl[0] = i; ctrl[1] = (int)(run - h); }
    }
    __syncthreads();
}

// =====================================================================
// Kernel 1: stream predictions; 4 tiles per block; hierarchical test
// =====================================================================
__device__ __forceinline__ void dec_push(float x, int col, int b, int a) {
    if (col >= 4 && x > PUSH_T) {
        int task = b * NCLS + (col - 4);
        float s = 1.0f / (1.0f + expf(-x));
        int idx = atomicAdd(&g_cnt[task * CNTSTR], 1);
        if (idx < CCAP) {
            unsigned key = __float_as_uint(s) | 0x80000000u;
            g_cand[(size_t)task * CCAP + idx] =
                ((unsigned long long)key << 32) | (unsigned)(~(unsigned)a);
        }
    }
}

__device__ __forceinline__ void dec_process(float4 v, int i, int b, int a0) {
    float m = fmaxf(fmaxf(v.x, v.y), fmaxf(v.z, v.w));
    if (m > PUSH_T) {
        int la   = i / 21;
        int col0 = (i - la * 21) * 4;
        int a    = a0 + la;
        dec_push(v.x, col0,     b, a);
        dec_push(v.y, col0 + 1, b, a);
        dec_push(v.z, col0 + 2, b, a);
        dec_push(v.w, col0 + 3, b, a);
    }
}

__global__ void __launch_bounds__(256) k_decode(const float* __restrict__ pred) {
    const int nBk = 600 / TILES_PB;              // 150 blocks per image
    const int b   = blockIdx.x / nBk;
    const int bt  = blockIdx.x % nBk;
    const int tid = threadIdx.x;

#pragma unroll
    for (int tt = 0; tt < TILES_PB; ++tt) {
        const int t  = bt * TILES_PB + tt;
        const int a0 = t << 7;
        const int na = min(128, A_N - a0);
        const float4* src = (const float4*)(pred + ((size_t)b * A_N + a0) * 84);
        const int tot = na * 21;

        int base = 0;
        for (; base + 1024 <= tot; base += 1024) {
            float4 v0 = src[base + tid];
            float4 v1 = src[base + tid + 256];
            float4 v2 = src[base + tid + 512];
            float4 v3 = src[base + tid + 768];
            dec_process(v0, base + tid,       b, a0);
            dec_process(v1, base + tid + 256, b, a0);
            dec_process(v2, base + tid + 512, b, a0);
            dec_process(v3, base + tid + 768, b, a0);
        }
        {
            int i0 = base + tid, i1 = i0 + 256, i2 = i1 + 256;
            float4 v0, v1, v2;
            bool p0 = i0 < tot, p1 = i1 < tot, p2 = i2 < tot;
            if (p0) v0 = src[i0];
            if (p1) v1 = src[i1];
            if (p2) v2 = src[i2];
            if (p0) dec_process(v0, i0, b, a0);
            if (p1) dec_process(v1, i1, b, a0);
            if (p2) dec_process(v2, i2, b, a0);
        }
    }
}

// =====================================================================
// Kernel 2: per (b,c) exact top-256 + greedy NMS + per-class top-100
// =====================================================================
__global__ void __launch_bounds__(256, 6) k_select(const float* __restrict__ pred,
                                                   const float* __restrict__ anchors) {
    extern __shared__ unsigned char sm[];
    unsigned*           hist = (unsigned*)sm;                      // 8KB
    unsigned*           csum = (unsigned*)(sm + 8192);             // 257 u32
    int*                ctrl = (int*)(sm + 9232);                  // 8 int
    unsigned long long* TIE  = (unsigned long long*)(sm + 9472);   // 32 u64
    unsigned long long* BUF  = (unsigned long long*)(sm + 9728);   // 8KB

    const int tid  = threadIdx.x;
    const int task = blockIdx.x;
    const int b    = task / NCLS;
    const int c    = task % NCLS;

    const int n = g_cnt[task * CNTSTR];
    bool fallback = !(n >= KPRE && n <= CCAP);
    const unsigned long long* cand = g_cand + (size_t)task * CCAP;

    for (int i = tid; i < NBIN2; i += 256) hist[i] = 0;
    if (tid < 8) ctrl[tid] = 0;
    __syncthreads();

    if (!fallback) {
        for (int i = tid; i < n; i += 256) {
            unsigned key = (unsigned)(cand[i] >> 32);
            unsigned bin = (key - SEL_BASE) >> 10; if (bin > 2047u) bin = 2047u;
            atomicAdd(&hist[bin], 1u);
        }
        __syncthreads();
        unsigned s8 = 0;
        {
            const int base = tid * 8;
#pragma unroll
            for (int r = 0; r < 8; ++r) s8 += hist[base + r];
        }
        unsigned incl = suffix_scan(s8, tid, csum);
        crossing2(hist, incl - s8, ctrl, KPRE, tid);
        const unsigned B1 = (unsigned)ctrl[0];
        const unsigned C1 = (unsigned)ctrl[1];
        const unsigned tie = hist[B1];
        __syncthreads();

        if (tie <= 32u) {
            if (tid == 0) { ctrl[2] = 0; ctrl[3] = 0; }
            __syncthreads();
            for (int i = tid; i < n; i += 256) {
                unsigned long long e = cand[i];
                unsigned key = (unsigned)(e >> 32);
                unsigned bin = (key - SEL_BASE) >> 10; if (bin > 2047u) bin = 2047u;
                if (bin > B1) {
                    int p = atomicAdd(&ctrl[2], 1);
                    BUF[p] = e;
                } else if (bin == B1) {
                    int q = atomicAdd(&ctrl[3], 1);
                    TIE[q] = e;
                }
            }
            __syncthreads();
            if (tid < 32) {
                const int t2 = ctrl[3];
                unsigned long long v = (tid < t2) ? TIE[tid] : 0ull;
#pragma unroll
                for (int k = 2; k <= 32; k <<= 1) {
#pragma unroll
                    for (int j = k >> 1; j > 0; j >>= 1) {
                        unsigned long long o = __shfl_xor_sync(0xFFFFFFFFu, v, j);
                        bool dir   = ((tid & k) == 0);
                        bool lower = ((tid & j) == 0);
                        bool keepMin = (lower == dir);
                        unsigned long long mn = v < o ? v : o;
                        unsigned long long mx = v < o ? o : v;
                        v = keepMin ? mn : mx;
                    }
                }
                int rankDesc = 31 - tid;
                int needTie = KPRE - (int)C1;
                if (rankDesc < needTie) BUF[C1 + rankDesc] = v;
            }
            __syncthreads();
            if (tid == 0) ctrl[2] = KPRE;
            __syncthreads();
        } else {
            const unsigned need = C1 + tie;
            if (need <= (unsigned)BUFN) {
                const unsigned minKey = SEL_BASE + (B1 << 10);
                if (tid == 0) ctrl[2] = 0;
                __syncthreads();
                for (int i = tid; i < n; i += 256) {
                    unsigned long long e = cand[i];
                    if ((unsigned)(e >> 32) >= minKey) {
                        int p = atomicAdd(&ctrl[2], 1);
                        BUF[p] = e;
                    }
                }
                __syncthreads();
            } else {
                fallback = true;
            }
        }
    }

    if (fallback) {
        for (int i = tid; i < NBIN2; i += 256) hist[i] = 0;
        if (tid < 8) ctrl[tid] = 0;
        __syncthreads();
        unsigned cnt = 0;
        for (int a = tid; a < A_N; a += 256) {
            float x = pred[((size_t)b * A_N + a) * 84 + 4 + c];
            float s = 1.0f / (1.0f + expf(-x));
            if (s > 0.05f) { ++cnt; atomicAdd(&hist[fkey32(s) >> 21], 1u); }
        }
        for (int o = 16; o; o >>= 1) cnt += __shfl_down_sync(0xFFFFFFFFu, cnt, o);
        if ((tid & 31) == 0) atomicAdd((unsigned*)&ctrl[5], cnt);
        __syncthreads();
        const unsigned total = (unsigned)ctrl[5];
        if (total == 0u) {
            for (int p = tid; p < MDPC; p += 256) {
                g_cls_scores[task * MDPC + p] = -1.0f;
                g_cls_boxes [task * MDPC + p] = make_float4(0.f, 0.f, 0.f, 0.f);
            }
            if (tid == 0) g_cnt[task * CNTSTR] = 0;
            return;
        }
        const unsigned target = total < (unsigned)KPRE ? total : (unsigned)KPRE;
        (void)suffix_total<8>(hist, csum, tid);
        crossing<8>(hist, csum, ctrl, target, tid);
        const unsigned B1 = (unsigned)ctrl[0];
        const unsigned C1 = (unsigned)ctrl[1];
        __syncthreads();
        for (int i = tid; i < NBIN2; i += 256) hist[i] = 0;
        __syncthreads();
        for (int a = tid; a < A_N; a += 256) {
            float x = pred[((size_t)b * A_N + a) * 84 + 4 + c];
            float s = 1.0f / (1.0f + expf(-x));
            if (s > 0.05f) {
                unsigned key = fkey32(s);
                if ((key >> 21) == B1) atomicAdd(&hist[(key >> 10) & 0x7FFu], 1u);
            }
        }
        __syncthreads();
        (void)suffix_total<8>(hist, csum, tid);
        crossing<8>(hist, csum, ctrl, target - C1, tid);
        const unsigned B2 = (unsigned)ctrl[0];
        if (tid == 0) ctrl[2] = 0;
        __syncthreads();
        for (int a = tid; a < A_N; a += 256) {
            float x = pred[((size_t)b * A_N + a) * 84 + 4 + c];
            float s = 1.0f / (1.0f + expf(-x));
            if (s > 0.05f) {
                unsigned key = fkey32(s);
                unsigned l1 = key >> 21;
                bool take = l1 > B1 || (l1 == B1 && ((key >> 10) & 0x7FFu) >= B2);
                if (take) {
                    int p = atomicAdd(&ctrl[2], 1);
                    if (p < BUFN)
                        BUF[p] = ((unsigned long long)key << 32) | (unsigned)(~(unsigned)a);
                }
            }
        }
        __syncthreads();
    }

    if (tid == 0) g_cnt[task * CNTSTR] = 0;      // reset for next graph replay

    int sel = ctrl[2]; if (sel > BUFN) sel = BUFN;
    const int W = (sel <= 256) ? 256 : ((sel <= 512) ? 512 : 1024);
    for (int i = sel + tid; i < W; i += 256) BUF[i] = 0ull;
    __syncthreads();

    for (int kk = 2; kk <= W; kk <<= 1) {
        for (int j = kk >> 1; j > 0; j >>= 1) {
            for (int i = tid; i < W; i += 256) {
                int ix = i ^ j;
                if (ix > i) {
                    unsigned long long x = BUF[i], y = BUF[ix];
                    bool sw = ((i & kk) == 0) ? (x < y) : (x > y);
                    if (sw) { BUF[i] = y; BUF[ix] = x; }
                }
            }
            __syncthreads();
        }
    }

    // ---- NMS on top-256 ----
    float4*   BXS   = (float4*)sm;               // [256] = 4KB
    float*    AR    = (float*)(sm + 4096);
    float*    SC    = (float*)(sm + 5120);
    unsigned* MASKS = (unsigned*)(sm + 6144);
    unsigned* KEEPW = (unsigned*)(sm + 14336);
    unsigned* WPFX  = (unsigned*)(sm + 14400);

    float ax1, ay1, ax2, ay2, aa;
    {
        unsigned long long e = BUF[tid];
        unsigned key  = (unsigned)(e >> 32);
        unsigned aidx = ~(unsigned)(e & 0xFFFFFFFFull);
        float  s  = -1.0f;
        float4 bx = make_float4(0.f, 0.f, 0.f, 0.f);
        if (key) {
            const float4 bp = *(const float4*)(pred + ((size_t)b * A_N + aidx) * 84);
            const float4 an = ((const float4*)anchors)[aidx];
            float cx = bp.x * 0.1f * an.z + an.x;
            float cy = bp.y * 0.1f * an.w + an.y;
            float w  = expf(bp.z * 0.2f) * an.z;
            float h  = expf(bp.w * 0.2f) * an.w;
            bx = make_float4(cx - w * 0.5f, cy - h * 0.5f, cx + w * 0.5f, cy + h * 0.5f);
            s  = __uint_as_float(key & 0x7FFFFFFFu);
        }
        BXS[tid] = bx;
        ax1 = bx.x; ay1 = bx.y; ax2 = bx.z; ay2 = bx.w;
        aa  = (bx.z - bx.x) * (bx.w - bx.y);
        AR[tid] = aa;
        SC[tid] = s;
        unsigned bal = __ballot_sync(0xFFFFFFFFu, key != 0u);
        if ((tid & 31) == 0) KEEPW[tid >> 5] = bal;
#pragma unroll
        for (int w = 0; w < 8; ++w) MASKS[tid * 8 + w] = 0u;
    }
    __syncthreads();

    {   // balanced all-pairs mask; test: 2*inter>u && inter>5e-9 (exact equiv)
        for (int k = 1; k <= 128; ++k) {
            if (k == 128 && tid >= 128) break;
            int j = (tid + k) & 255;
            float4 bj = BXS[j];
            float iw = fmaxf(fminf(ax2, bj.z) - fmaxf(ax1, bj.x), 0.f);
            float ih = fmaxf(fminf(ay2, bj.w) - fmaxf(ay1, bj.y), 0.f);
            float inter = iw * ih;
            float u = aa + (bj.z - bj.x) * (bj.w - bj.y) - inter;
            if (inter + inter > u && inter > 5e-9f) {
                int lo = tid < j ? tid : j;
                int hi = tid ^ j ^ lo;
                atomicOr(&MASKS[lo * 8 + (hi >> 5)], 1u << (hi & 31));
            }
        }
    }
    __syncthreads();

    if (tid < 32) {
        unsigned kw = (tid < 8) ? KEEPW[tid] : 0u;
        int kcnt = 0;
        for (int i = 0; i < 256 && kcnt < MDPC; ++i) {
            unsigned word = __shfl_sync(0xFFFFFFFFu, kw, i >> 5);
            if ((word >> (i & 31)) & 1u) {
                ++kcnt;
                if (tid < 8) kw &= ~MASKS[i * 8 + tid];
            }
        }
        if (tid < 8) KEEPW[tid] = kw;
    }
    __syncthreads();

    if (tid == 0) {
        unsigned run = 0;
        for (int w = 0; w < 8; ++w) { WPFX[w] = run; run += __popc(KEEPW[w]); }
        WPFX[8] = run;
    }
    __syncthreads();

    {
        unsigned w = tid >> 5, bpos = tid & 31;
        unsigned kwv = KEEPW[w];
        bool kept = (kwv >> bpos) & 1u;
        unsigned p = WPFX[w] + __popc(kwv & ((1u << bpos) - 1u));
        if (kept && p < MDPC) {
            g_cls_scores[task * MDPC + p] = SC[tid];
            g_cls_boxes [task * MDPC + p] = BXS[tid];
        }
        int kc = (int)WPFX[8];
        for (int q = kc + tid; q < MDPC; q += 256) {
            g_cls_scores[task * MDPC + q] = -1.0f;
            g_cls_boxes [task * MDPC + q] = make_float4(0.f, 0.f, 0.f, 0.f);
        }
    }
}

// =====================================================================
// Kernel 3: per image top-100 of 8000
// =====================================================================
__global__ void __launch_bounds__(256) k_final(float* __restrict__ out) {
    __shared__ unsigned hist[NBINF];
    __shared__ unsigned long long BUF[256];
    __shared__ unsigned csum[257];
    __shared__ int ctrl[8];
    __shared__ int vc;

    const int tid = threadIdx.x;
    const int b   = blockIdx.x;
    const float* sc = g_cls_scores + b * NCLS * MDPC;

    for (int i = tid; i < NBINF; i += 256) hist[i] = 0;
    if (tid < 8) ctrl[tid] = 0;
    __syncthreads();

    unsigned cnt = 0;
    for (int i = tid; i < NCLS * MDPC; i += 256) {
        float s = sc[i];
        if (s > 0.0f) { ++cnt; atomicAdd(&hist[(fkey32(s) - FIN_BASE) >> 14], 1u); }
    }
    for (int o = 16; o; o >>= 1) cnt += __shfl_down_sync(0xFFFFFFFFu, cnt, o);
    if ((tid & 31) == 0) atomicAdd((unsigned*)&ctrl[5], cnt);
    __syncthreads();
    const unsigned npos = (unsigned)ctrl[5];

    if (npos >= (unsigned)MAXD) {
        (void)suffix_total<16>(hist, csum, tid);
        crossing<16>(hist, csum, ctrl, MAXD, tid);
        const unsigned B1 = (unsigned)ctrl[0];
        const unsigned C1 = (unsigned)ctrl[1];
        __syncthreads();
        for (int i = tid; i < NBINF; i += 256) hist[i] = 0;
        __syncthreads();
        for (int i = tid; i < NCLS * MDPC; i += 256) {
            float s = sc[i];
            if (s > 0.0f) {
                unsigned key = fkey32(s);
                if (((key - FIN_BASE) >> 14) == B1) atomicAdd(&hist[(key >> 2) & 0xFFFu], 1u);
            }
        }
        __syncthreads();
        (void)suffix_total<16>(hist, csum, tid);
        crossing<16>(hist, csum, ctrl, MAXD - C1, tid);
        const unsigned B2 = (unsigned)ctrl[0];
        if (tid == 0) ctrl[2] = 0;
        __syncthreads();
        for (int i = tid; i < NCLS * MDPC; i += 256) {
            float s = sc[i];
            if (s > 0.0f) {
                unsigned key = fkey32(s);
                unsigned l1 = (key - FIN_BASE) >> 14;
                bool take = l1 > B1 || (l1 == B1 && ((key >> 2) & 0xFFFu) >= B2);
                if (take) {
                    int p = atomicAdd(&ctrl[2], 1);
                    if (p < 256)
                        BUF[p] = ((unsigned long long)key << 32) | (unsigned)(~(unsigned)i);
                }
            }
        }
        __syncthreads();
    } else {
        if (tid == 0) ctrl[2] = 0;
        __syncthreads();
        for (int i = tid; i < NCLS * MDPC; i += 256) {
            float s = sc[i];
            if (s > 0.0f) {
                int p = atomicAdd(&ctrl[2], 1);
                if (p < 256)
                    BUF[p] = ((unsigned long long)fkey32(s) << 32) | (unsigned)(~(unsigned)i);
            }
        }
        __syncthreads();
    }

    int sel = ctrl[2]; if (sel > 256) sel = 256;
    if (tid >= sel) BUF[tid] = 0ull;
    __syncthreads();

    for (int kk = 2; kk <= 256; kk <<= 1) {
        for (int j = kk >> 1; j > 0; j >>= 1) {
            int ix = tid ^ j;
            if (ix > tid) {
                unsigned long long x = BUF[tid], y = BUF[ix];
                bool sw = ((tid & kk) == 0) ? (x < y) : (x > y);
                if (sw) { BUF[tid] = y; BUF[ix] = x; }
            }
            __syncthreads();
        }
    }

    if (tid == 0) vc = 0;
    __syncthreads();

    if (tid < MAXD) {
        unsigned long long e = BUF[tid];
        unsigned key  = (unsigned)(e >> 32);
        unsigned flat = ~(unsigned)(e & 0xFFFFFFFFull);
        bool valid = (key != 0u);
        float4 bx = make_float4(0.f, 0.f, 0.f, 0.f);
        float cls = 0.0f, so = 0.0f;
        if (valid) {
            float s = __uint_as_float((key & 0x80000000u) ? (key & 0x7FFFFFFFu) : ~key);
            bx  = g_cls_boxes[b * NCLS * MDPC + flat];
            cls = (float)(flat / MDPC);
            so  = s;
            atomicAdd(&vc, 1);
        }
        out[b * 400 + tid * 4 + 0] = bx.x;
        out[b * 400 + tid * 4 + 1] = bx.y;
        out[b * 400 + tid * 4 + 2] = bx.z;
        out[b * 400 + tid * 4 + 3] = bx.w;
        out[NB * MAXD * 4 + b * MAXD + tid]             = so;
        out[NB * MAXD * 4 + NB * MAXD + b * MAXD + tid] = cls;
    }
    __syncthreads();
    if (tid == 0) out[NB * MAXD * 6 + b] = (float)vc;
}

// =====================================================================
extern "C" void kernel_launch(void* const* d_in, const int* in_sizes, int n_in,
                              void* d_out, int out_size) {
    (void)in_sizes; (void)n_in; (void)out_size;
    const float* pred    = (const float*)d_in[1];
    const float* anchors = (const float*)d_in[2];
    float* out = (float*)d_out;

    k_decode<<<NB * (600 / TILES_PB), 256>>>(pred);

    cudaFuncSetAttribute(k_select, cudaFuncAttributeMaxDynamicSharedMemorySize, 17920);
    k_select<<<NTASK, 256, 17920>>>(pred, anchors);

    k_final<<<NB, 256>>>(out);
}

// round 15
// speedup vs baseline: 1.4397x; 1.4397x over previous
#include <cuda_runtime.h>
#include <math.h>

#define A_N    76725
#define NCLS   80
#define NB     8
#define NTASK  (NB*NCLS)
#define KPRE   256
#define MDPC   100
#define MAXD   100
#define CCAP   3072
#define BUFN   1024
#define NBIN2  2048
#define NBINF  4096
#define PUSH_T 2.5f
#define CNTSTR 32
#define SEL_BASE 0xBF600000u
#define FIN_BASE 0xBD400000u

__device__ unsigned long long g_cand[(size_t)NTASK * CCAP];
__device__ int    g_cnt[NTASK * CNTSTR];        // zero-init; k_select resets after use
__device__ float  g_cls_scores[NTASK * MDPC];
__device__ float4 g_cls_boxes[NTASK * MDPC];

__device__ __forceinline__ unsigned fkey32(float x) {
    unsigned b = __float_as_uint(x);
    return (b & 0x80000000u) ? ~b : (b | 0x80000000u);
}

// legacy barrier-scan (fallback + k_final)
template <int BPT>
__device__ __forceinline__ unsigned suffix_total(const unsigned* hist, unsigned* csum, int tid) {
    unsigned s = 0;
    const int base = tid * BPT;
#pragma unroll
    for (int r = 0; r < BPT; ++r) s += hist[base + r];
    csum[tid] = s;
    __syncthreads();
    for (int off = 1; off < 256; off <<= 1) {
        unsigned add = (tid + off < 256) ? csum[tid + off] : 0u;
        __syncthreads();
        csum[tid] += add;
        __syncthreads();
    }
    return csum[0];
}

template <int BPT>
__device__ __forceinline__ void crossing(const unsigned* hist, const unsigned* csum, int* ctrl,
                                         unsigned target, int tid) {
    unsigned run = (tid + 1 < 256) ? csum[tid + 1] : 0u;
    const int base = tid * BPT;
    for (int i = base + BPT - 1; i >= base; --i) {
        unsigned h = hist[i];
        run += h;
        if (run >= target && run - h < target) { ctrl[0] = i; ctrl[1] = (int)(run - h); }
    }
    __syncthreads();
}

// shuffle-based inclusive suffix over 256 per-thread sums; 2 barriers.
__device__ __forceinline__ unsigned suffix_scan(unsigned s, int tid, volatile unsigned* wtot) {
    unsigned v = s;
    const int lane = tid & 31;
#pragma unroll
    for (int off = 1; off < 32; off <<= 1) {
        unsigned t = __shfl_down_sync(0xFFFFFFFFu, v, off);
        if (lane + off < 32) v += t;
    }
    const int w = tid >> 5;
    if (lane == 0) wtot[w] = v;
    __syncthreads();
    if (tid == 0) {
        unsigned run = 0;
        for (int i = 7; i >= 0; --i) { unsigned t2 = wtot[i]; wtot[i] = run; run += t2; }
        wtot[8] = run;
    }
    __syncthreads();
    return v + wtot[w];
}

__device__ __forceinline__ void crossing2(const unsigned* hist, unsigned runstart, int* ctrl,
                                          unsigned target, int tid) {
    unsigned run = runstart;
    const int base = tid * 8;
#pragma unroll
    for (int i = base + 7; i >= base; --i) {
        unsigned h = hist[i];
        run += h;
        if (run >= target && run - h < target) { ctrl[0] = i; ctrl[1] = (int)(run - h); }
    }
    __syncthreads();
}

// =====================================================================
// Kernel 1: stream predictions; one 128-anchor tile per block (R13 shape)
// =====================================================================
__device__ __forceinline__ void dec_push(float x, int col, int b, int a) {
    if (col >= 4 && x > PUSH_T) {
        int task = b * NCLS + (col - 4);
        float s = 1.0f / (1.0f + expf(-x));
        int idx = atomicAdd(&g_cnt[task * CNTSTR], 1);
        if (idx < CCAP) {
            unsigned key = __float_as_uint(s) | 0x80000000u;
            g_cand[(size_t)task * CCAP + idx] =
                ((unsigned long long)key << 32) | (unsigned)(~(unsigned)a);
        }
    }
}

__device__ __forceinline__ void dec_process(float4 v, int i, int b, int a0) {
    float m = fmaxf(fmaxf(v.x, v.y), fmaxf(v.z, v.w));
    if (m > PUSH_T) {
        int la   = i / 21;
        int col0 = (i - la * 21) * 4;
        int a    = a0 + la;
        dec_push(v.x, col0,     b, a);
        dec_push(v.y, col0 + 1, b, a);
        dec_push(v.z, col0 + 2, b, a);
        dec_push(v.w, col0 + 3, b, a);
    }
}

__global__ void __launch_bounds__(256) k_decode(const float* __restrict__ pred) {
    const int nT = 600;
    const int b  = blockIdx.x / nT;
    const int t  = blockIdx.x % nT;
    const int a0 = t << 7;
    const int na = min(128, A_N - a0);
    const float4* src = (const float4*)(pred + ((size_t)b * A_N + a0) * 84);
    const int tid = threadIdx.x;
    const int tot = na * 21;

    int base = 0;
    for (; base + 1024 <= tot; base += 1024) {
        float4 v0 = src[base + tid];
        float4 v1 = src[base + tid + 256];
        float4 v2 = src[base + tid + 512];
        float4 v3 = src[base + tid + 768];
        dec_process(v0, base + tid,       b, a0);
        dec_process(v1, base + tid + 256, b, a0);
        dec_process(v2, base + tid + 512, b, a0);
        dec_process(v3, base + tid + 768, b, a0);
    }
    {
        int i0 = base + tid, i1 = i0 + 256, i2 = i1 + 256;
        float4 v0, v1, v2;
        bool p0 = i0 < tot, p1 = i1 < tot, p2 = i2 < tot;
        if (p0) v0 = src[i0];
        if (p1) v1 = src[i1];
        if (p2) v2 = src[i2];
        if (p0) dec_process(v0, i0, b, a0);
        if (p1) dec_process(v1, i1, b, a0);
        if (p2) dec_process(v2, i2, b, a0);
    }
}

// =====================================================================
// Kernel 2: per (b,c) exact top-256 + greedy NMS + per-class top-100
// =====================================================================
__global__ void __launch_bounds__(256, 6) k_select(const float* __restrict__ pred,
                                                   const float* __restrict__ anchors) {
    extern __shared__ unsigned char sm[];
    unsigned*           hist = (unsigned*)sm;                      // 8KB
    unsigned*           csum = (unsigned*)(sm + 8192);             // 257 u32
    int*                ctrl = (int*)(sm + 9232);                  // 8 int
    unsigned long long* TIE  = (unsigned long long*)(sm + 9472);   // 32 u64
    unsigned long long* BUF  = (unsigned long long*)(sm + 9728);   // 8KB

    const int tid  = threadIdx.x;
    const int task = blockIdx.x;
    const int b    = task / NCLS;
    const int c    = task % NCLS;

    const int n = g_cnt[task * CNTSTR];
    bool fallback = !(n >= KPRE && n <= CCAP);
    const unsigned long long* cand = g_cand + (size_t)task * CCAP;

    for (int i = tid; i < NBIN2; i += 256) hist[i] = 0;
    if (tid < 8) ctrl[tid] = 0;
    __syncthreads();

    if (!fallback) {
        for (int i = tid; i < n; i += 256) {
            unsigned key = (unsigned)(cand[i] >> 32);
            unsigned bin = (key - SEL_BASE) >> 10; if (bin > 2047u) bin = 2047u;
            atomicAdd(&hist[bin], 1u);
        }
        __syncthreads();
        unsigned s8 = 0;
        {
            const int base = tid * 8;
#pragma unroll
            for (int r = 0; r < 8; ++r) s8 += hist[base + r];
        }
        unsigned incl = suffix_scan(s8, tid, csum);
        crossing2(hist, incl - s8, ctrl, KPRE, tid);
        const unsigned B1 = (unsigned)ctrl[0];
        const unsigned C1 = (unsigned)ctrl[1];
        const unsigned tie = hist[B1];
        __syncthreads();

        if (tie <= 32u) {
            if (tid == 0) { ctrl[2] = 0; ctrl[3] = 0; }
            __syncthreads();
            for (int i = tid; i < n; i += 256) {
                unsigned long long e = cand[i];
                unsigned key = (unsigned)(e >> 32);
                unsigned bin = (key - SEL_BASE) >> 10; if (bin > 2047u) bin = 2047u;
                if (bin > B1) {
                    int p = atomicAdd(&ctrl[2], 1);
                    BUF[p] = e;
                } else if (bin == B1) {
                    int q = atomicAdd(&ctrl[3], 1);
                    TIE[q] = e;
                }
            }
            __syncthreads();
            if (tid < 32) {
                const int t2 = ctrl[3];
                unsigned long long v = (tid < t2) ? TIE[tid] : 0ull;
#pragma unroll
                for (int k = 2; k <= 32; k <<= 1) {
#pragma unroll
                    for (int j = k >> 1; j > 0; j >>= 1) {
                        unsigned long long o = __shfl_xor_sync(0xFFFFFFFFu, v, j);
                        bool dir   = ((tid & k) == 0);
                        bool lower = ((tid & j) == 0);
                        bool keepMin = (lower == dir);
                        unsigned long long mn = v < o ? v : o;
                        unsigned long long mx = v < o ? o : v;
                        v = keepMin ? mn : mx;
                    }
                }
                int rankDesc = 31 - tid;
                int needTie = KPRE - (int)C1;
                if (rankDesc < needTie) BUF[C1 + rankDesc] = v;
            }
            __syncthreads();
            if (tid == 0) ctrl[2] = KPRE;
            __syncthreads();
        } else {
            const unsigned need = C1 + tie;
            if (need <= (unsigned)BUFN) {
                const unsigned minKey = SEL_BASE + (B1 << 10);
                if (tid == 0) ctrl[2] = 0;
                __syncthreads();
                for (int i = tid; i < n; i += 256) {
                    unsigned long long e = cand[i];
                    if ((unsigned)(e >> 32) >= minKey) {
                        int p = atomicAdd(&ctrl[2], 1);
                        BUF[p] = e;
                    }
                }
                __syncthreads();
            } else {
                fallback = true;
            }
        }
    }

    if (fallback) {
        for (int i = tid; i < NBIN2; i += 256) hist[i] = 0;
        if (tid < 8) ctrl[tid] = 0;
        __syncthreads();
        unsigned cnt = 0;
        for (int a = tid; a < A_N; a += 256) {
            float x = pred[((size_t)b * A_N + a) * 84 + 4 + c];
            float s = 1.0f / (1.0f + expf(-x));
            if (s > 0.05f) { ++cnt; atomicAdd(&hist[fkey32(s) >> 21], 1u); }
        }
        for (int o = 16; o; o >>= 1) cnt += __shfl_down_sync(0xFFFFFFFFu, cnt, o);
        if ((tid & 31) == 0) atomicAdd((unsigned*)&ctrl[5], cnt);
        __syncthreads();
        const unsigned total = (unsigned)ctrl[5];
        if (total == 0u) {
            for (int p = tid; p < MDPC; p += 256) {
                g_cls_scores[task * MDPC + p] = -1.0f;
                g_cls_boxes [task * MDPC + p] = make_float4(0.f, 0.f, 0.f, 0.f);
            }
            if (tid == 0) g_cnt[task * CNTSTR] = 0;
            return;
        }
        const unsigned target = total < (unsigned)KPRE ? total : (unsigned)KPRE;
        (void)suffix_total<8>(hist, csum, tid);
        crossing<8>(hist, csum, ctrl, target, tid);
        const unsigned B1 = (unsigned)ctrl[0];
        const unsigned C1 = (unsigned)ctrl[1];
        __syncthreads();
        for (int i = tid; i < NBIN2; i += 256) hist[i] = 0;
        __syncthreads();
        for (int a = tid; a < A_N; a += 256) {
            float x = pred[((size_t)b * A_N + a) * 84 + 4 + c];
            float s = 1.0f / (1.0f + expf(-x));
            if (s > 0.05f) {
                unsigned key = fkey32(s);
                if ((key >> 21) == B1) atomicAdd(&hist[(key >> 10) & 0x7FFu], 1u);
            }
        }
        __syncthreads();
        (void)suffix_total<8>(hist, csum, tid);
        crossing<8>(hist, csum, ctrl, target - C1, tid);
        const unsigned B2 = (unsigned)ctrl[0];
        if (tid == 0) ctrl[2] = 0;
        __syncthreads();
        for (int a = tid; a < A_N; a += 256) {
            float x = pred[((size_t)b * A_N + a) * 84 + 4 + c];
            float s = 1.0f / (1.0f + expf(-x));
            if (s > 0.05f) {
                unsigned key = fkey32(s);
                unsigned l1 = key >> 21;
                bool take = l1 > B1 || (l1 == B1 && ((key >> 10) & 0x7FFu) >= B2);
                if (take) {
                    int p = atomicAdd(&ctrl[2], 1);
                    if (p < BUFN)
                        BUF[p] = ((unsigned long long)key << 32) | (unsigned)(~(unsigned)a);
                }
            }
        }
        __syncthreads();
    }

    if (tid == 0) g_cnt[task * CNTSTR] = 0;      // reset for next graph replay

    int sel = ctrl[2]; if (sel > BUFN) sel = BUFN;
    const int W = (sel <= 256) ? 256 : ((sel <= 512) ? 512 : 1024);
    for (int i = sel + tid; i < W; i += 256) BUF[i] = 0ull;
    __syncthreads();

    for (int kk = 2; kk <= W; kk <<= 1) {
        for (int j = kk >> 1; j > 0; j >>= 1) {
            for (int i = tid; i < W; i += 256) {
                int ix = i ^ j;
                if (ix > i) {
                    unsigned long long x = BUF[i], y = BUF[ix];
                    bool sw = ((i & kk) == 0) ? (x < y) : (x > y);
                    if (sw) { BUF[i] = y; BUF[ix] = x; }
                }
            }
            __syncthreads();
        }
    }

    // ---- NMS on top-256 ----
    float4*   BXS   = (float4*)sm;               // [256] = 4KB
    float*    AR    = (float*)(sm + 4096);
    float*    SC    = (float*)(sm + 5120);
    unsigned* MASKS = (unsigned*)(sm + 6144);
    unsigned* KEEPW = (unsigned*)(sm + 14336);
    unsigned* WPFX  = (unsigned*)(sm + 14400);

    float ax1, ay1, ax2, ay2, aa;
    {
        unsigned long long e = BUF[tid];
        unsigned key  = (unsigned)(e >> 32);
        unsigned aidx = ~(unsigned)(e & 0xFFFFFFFFull);
        float  s  = -1.0f;
        float4 bx = make_float4(0.f, 0.f, 0.f, 0.f);
        if (key) {
            const float4 bp = *(const float4*)(pred + ((size_t)b * A_N + aidx) * 84);
            const float4 an = ((const float4*)anchors)[aidx];
            float cx = bp.x * 0.1f * an.z + an.x;
            float cy = bp.y * 0.1f * an.w + an.y;
            float w  = expf(bp.z * 0.2f) * an.z;
            float h  = expf(bp.w * 0.2f) * an.w;
            bx = make_float4(cx - w * 0.5f, cy - h * 0.5f, cx + w * 0.5f, cy + h * 0.5f);
            s  = __uint_as_float(key & 0x7FFFFFFFu);
        }
        BXS[tid] = bx;
        ax1 = bx.x; ay1 = bx.y; ax2 = bx.z; ay2 = bx.w;
        aa  = (bx.z - bx.x) * (bx.w - bx.y);
        AR[tid] = aa;
        SC[tid] = s;
        unsigned bal = __ballot_sync(0xFFFFFFFFu, key != 0u);
        if ((tid & 31) == 0) KEEPW[tid >> 5] = bal;
#pragma unroll
        for (int w = 0; w < 8; ++w) MASKS[tid * 8 + w] = 0u;
    }
    __syncthreads();

    {   // balanced all-pairs mask; test: 2*inter>u && inter>5e-9 (exact equiv)
        for (int k = 1; k <= 128; ++k) {
            if (k == 128 && tid >= 128) break;
            int j = (tid + k) & 255;
            float4 bj = BXS[j];
            float iw = fmaxf(fminf(ax2, bj.z) - fmaxf(ax1, bj.x), 0.f);
            float ih = fmaxf(fminf(ay2, bj.w) - fmaxf(ay1, bj.y), 0.f);
            float inter = iw * ih;
            float u = aa + (bj.z - bj.x) * (bj.w - bj.y) - inter;
            if (inter + inter > u && inter > 5e-9f) {
                int lo = tid < j ? tid : j;
                int hi = tid ^ j ^ lo;
                atomicOr(&MASKS[lo * 8 + (hi >> 5)], 1u << (hi & 31));
            }
        }
    }
    __syncthreads();

    if (tid < 32) {
        unsigned kw = (tid < 8) ? KEEPW[tid] : 0u;
        int kcnt = 0;
        for (int i = 0; i < 256 && kcnt < MDPC; ++i) {
            unsigned word = __shfl_sync(0xFFFFFFFFu, kw, i >> 5);
            if ((word >> (i & 31)) & 1u) {
                ++kcnt;
                if (tid < 8) kw &= ~MASKS[i * 8 + tid];
            }
        }
        if (tid < 8) KEEPW[tid] = kw;
    }
    __syncthreads();

    if (tid == 0) {
        unsigned run = 0;
        for (int w = 0; w < 8; ++w) { WPFX[w] = run; run += __popc(KEEPW[w]); }
        WPFX[8] = run;
    }
    __syncthreads();

    {
        unsigned w = tid >> 5, bpos = tid & 31;
        unsigned kwv = KEEPW[w];
        bool kept = (kwv >> bpos) & 1u;
        unsigned p = WPFX[w] + __popc(kwv & ((1u << bpos) - 1u));
        if (kept && p < MDPC) {
            g_cls_scores[task * MDPC + p] = SC[tid];
            g_cls_boxes [task * MDPC + p] = BXS[tid];
        }
        int kc = (int)WPFX[8];
        for (int q = kc + tid; q < MDPC; q += 256) {
            g_cls_scores[task * MDPC + q] = -1.0f;
            g_cls_boxes [task * MDPC + q] = make_float4(0.f, 0.f, 0.f, 0.f);
        }
    }
}

// =====================================================================
// Kernel 3: per image top-100 of 8000
// =====================================================================
__global__ void __launch_bounds__(256) k_final(float* __restrict__ out) {
    __shared__ unsigned hist[NBINF];
    __shared__ unsigned long long BUF[256];
    __shared__ unsigned csum[257];
    __shared__ int ctrl[8];
    __shared__ int vc;

    const int tid = threadIdx.x;
    const int b   = blockIdx.x;
    const float* sc = g_cls_scores + b * NCLS * MDPC;

    for (int i = tid; i < NBINF; i += 256) hist[i] = 0;
    if (tid < 8) ctrl[tid] = 0;
    __syncthreads();

    unsigned cnt = 0;
    for (int i = tid; i < NCLS * MDPC; i += 256) {
        float s = sc[i];
        if (s > 0.0f) { ++cnt; atomicAdd(&hist[(fkey32(s) - FIN_BASE) >> 14], 1u); }
    }
    for (int o = 16; o; o >>= 1) cnt += __shfl_down_sync(0xFFFFFFFFu, cnt, o);
    if ((tid & 31) == 0) atomicAdd((unsigned*)&ctrl[5], cnt);
    __syncthreads();
    const unsigned npos = (unsigned)ctrl[5];

    if (npos >= (unsigned)MAXD) {
        (void)suffix_total<16>(hist, csum, tid);
        crossing<16>(hist, csum, ctrl, MAXD, tid);
        const unsigned B1 = (unsigned)ctrl[0];
        const unsigned C1 = (unsigned)ctrl[1];
        __syncthreads();
        for (int i = tid; i < NBINF; i += 256) hist[i] = 0;
        __syncthreads();
        for (int i = tid; i < NCLS * MDPC; i += 256) {
            float s = sc[i];
            if (s > 0.0f) {
                unsigned key = fkey32(s);
                if (((key - FIN_BASE) >> 14) == B1) atomicAdd(&hist[(key >> 2) & 0xFFFu], 1u);
            }
        }
        __syncthreads();
        (void)suffix_total<16>(hist, csum, tid);
        crossing<16>(hist, csum, ctrl, MAXD - C1, tid);
        const unsigned B2 = (unsigned)ctrl[0];
        if (tid == 0) ctrl[2] = 0;
        __syncthreads();
        for (int i = tid; i < NCLS * MDPC; i += 256) {
            float s = sc[i];
            if (s > 0.0f) {
                unsigned key = fkey32(s);
                unsigned l1 = (key - FIN_BASE) >> 14;
                bool take = l1 > B1 || (l1 == B1 && ((key >> 2) & 0xFFFu) >= B2);
                if (take) {
                    int p = atomicAdd(&ctrl[2], 1);
                    if (p < 256)
                        BUF[p] = ((unsigned long long)key << 32) | (unsigned)(~(unsigned)i);
                }
            }
        }
        __syncthreads();
    } else {
        if (tid == 0) ctrl[2] = 0;
        __syncthreads();
        for (int i = tid; i < NCLS * MDPC; i += 256) {
            float s = sc[i];
            if (s > 0.0f) {
                int p = atomicAdd(&ctrl[2], 1);
                if (p < 256)
                    BUF[p] = ((unsigned long long)fkey32(s) << 32) | (unsigned)(~(unsigned)i);
            }
        }
        __syncthreads();
    }

    int sel = ctrl[2]; if (sel > 256) sel = 256;
    if (tid >= sel) BUF[tid] = 0ull;
    __syncthreads();

    for (int kk = 2; kk <= 256; kk <<= 1) {
        for (int j = kk >> 1; j > 0; j >>= 1) {
            int ix = tid ^ j;
            if (ix > tid) {
                unsigned long long x = BUF[tid], y = BUF[ix];
                bool sw = ((tid & kk) == 0) ? (x < y) : (x > y);
                if (sw) { BUF[tid] = y; BUF[ix] = x; }
            }
            __syncthreads();
        }
    }

    if (tid == 0) vc = 0;
    __syncthreads();

    if (tid < MAXD) {
        unsigned long long e = BUF[tid];
        unsigned key  = (unsigned)(e >> 32);
        unsigned flat = ~(unsigned)(e & 0xFFFFFFFFull);
        bool valid = (key != 0u);
        float4 bx = make_float4(0.f, 0.f, 0.f, 0.f);
        float cls = 0.0f, so = 0.0f;
        if (valid) {
            float s = __uint_as_float((key & 0x80000000u) ? (key & 0x7FFFFFFFu) : ~key);
            bx  = g_cls_boxes[b * NCLS * MDPC + flat];
            cls = (float)(flat / MDPC);
            so  = s;
            atomicAdd(&vc, 1);
        }
        out[b * 400 + tid * 4 + 0] = bx.x;
        out[b * 400 + tid * 4 + 1] = bx.y;
        out[b * 400 + tid * 4 + 2] = bx.z;
        out[b * 400 + tid * 4 + 3] = bx.w;
        out[NB * MAXD * 4 + b * MAXD + tid]             = so;
        out[NB * MAXD * 4 + NB * MAXD + b * MAXD + tid] = cls;
    }
    __syncthreads();
    if (tid == 0) out[NB * MAXD * 6 + b] = (float)vc;
}

// =====================================================================
extern "C" void kernel_launch(void* const* d_in, const int* in_sizes, int n_in,
                              void* d_out, int out_size) {
    (void)in_sizes; (void)n_in; (void)out_size;
    const float* pred    = (const float*)d_in[1];
    const float* anchors = (const float*)d_in[2];
    float* out = (float*)d_out;

    k_decode<<<NB * 600, 256>>>(pred);

    cudaFuncSetAttribute(k_select, cudaFuncAttributeMaxDynamicSharedMemorySize, 17920);
    k_select<<<NTASK, 256, 17920>>>(pred, anchors);

    k_final<<<NB, 256>>>(out);
}

// round 16
// speedup vs baseline: 1.4745x; 1.0242x over previous
#include <cuda_runtime.h>
#include <math.h>

#define A_N    76725
#define NCLS   80
#define NB     8
#define NTASK  (NB*NCLS)
#define KPRE   256
#define MDPC   100
#define MAXD   100
#define CCAP   3072
#define BUFN   1024
#define NBIN2  2048
#define NBINF  4096
#define PUSH_T 2.5f
#define CNTSTR 32
#define SEL_BASE 0xBF600000u
#define FIN_BASE 0xBD400000u

__device__ unsigned long long g_cand[(size_t)NTASK * CCAP];
__device__ int    g_cnt[NTASK * CNTSTR];        // zero-init; k_select resets after use
__device__ float  g_cls_scores[NTASK * MDPC];
__device__ float4 g_cls_boxes[NTASK * MDPC];

__device__ __forceinline__ unsigned fkey32(float x) {
    unsigned b = __float_as_uint(x);
    return (b & 0x80000000u) ? ~b : (b | 0x80000000u);
}

// legacy barrier-scan (fallback + k_final)
template <int BPT>
__device__ __forceinline__ unsigned suffix_total(const unsigned* hist, unsigned* csum, int tid) {
    unsigned s = 0;
    const int base = tid * BPT;
#pragma unroll
    for (int r = 0; r < BPT; ++r) s += hist[base + r];
    csum[tid] = s;
    __syncthreads();
    for (int off = 1; off < 256; off <<= 1) {
        unsigned add = (tid + off < 256) ? csum[tid + off] : 0u;
        __syncthreads();
        csum[tid] += add;
        __syncthreads();
    }
    return csum[0];
}

template <int BPT>
__device__ __forceinline__ void crossing(const unsigned* hist, const unsigned* csum, int* ctrl,
                                         unsigned target, int tid) {
    unsigned run = (tid + 1 < 256) ? csum[tid + 1] : 0u;
    const int base = tid * BPT;
    for (int i = base + BPT - 1; i >= base; --i) {
        unsigned h = hist[i];
        run += h;
        if (run >= target && run - h < target) { ctrl[0] = i; ctrl[1] = (int)(run - h); }
    }
    __syncthreads();
}

// shuffle-based inclusive suffix over 256 per-thread sums; 2 barriers.
__device__ __forceinline__ unsigned suffix_scan(unsigned s, int tid, volatile unsigned* wtot) {
    unsigned v = s;
    const int lane = tid & 31;
#pragma unroll
    for (int off = 1; off < 32; off <<= 1) {
        unsigned t = __shfl_down_sync(0xFFFFFFFFu, v, off);
        if (lane + off < 32) v += t;
    }
    const int w = tid >> 5;
    if (lane == 0) wtot[w] = v;
    __syncthreads();
    if (tid == 0) {
        unsigned run = 0;
        for (int i = 7; i >= 0; --i) { unsigned t2 = wtot[i]; wtot[i] = run; run += t2; }
        wtot[8] = run;
    }
    __syncthreads();
    return v + wtot[w];
}

__device__ __forceinline__ void crossing2(const unsigned* hist, unsigned runstart, int* ctrl,
                                          unsigned target, int tid) {
    unsigned run = runstart;
    const int base = tid * 8;
#pragma unroll
    for (int i = base + 7; i >= base; --i) {
        unsigned h = hist[i];
        run += h;
        if (run >= target && run - h < target) { ctrl[0] = i; ctrl[1] = (int)(run - h); }
    }
    __syncthreads();
}

// =====================================================================
// Kernel 1: stream predictions; 384 threads, exactly 7 strides, no tail
// =====================================================================
__device__ __forceinline__ void dec_push(float x, int col, int b, int a) {
    if (col >= 4 && x > PUSH_T) {
        int task = b * NCLS + (col - 4);
        float s = 1.0f / (1.0f + expf(-x));
        int idx = atomicAdd(&g_cnt[task * CNTSTR], 1);
        if (idx < CCAP) {
            unsigned key = __float_as_uint(s) | 0x80000000u;
            g_cand[(size_t)task * CCAP + idx] =
                ((unsigned long long)key << 32) | (unsigned)(~(unsigned)a);
        }
    }
}

__device__ __forceinline__ void dec_process(float4 v, int i, int b, int a0) {
    float m = fmaxf(fmaxf(v.x, v.y), fmaxf(v.z, v.w));
    if (m > PUSH_T) {
        int la   = i / 21;
        int col0 = (i - la * 21) * 4;
        int a    = a0 + la;
        dec_push(v.x, col0,     b, a);
        dec_push(v.y, col0 + 1, b, a);
        dec_push(v.z, col0 + 2, b, a);
        dec_push(v.w, col0 + 3, b, a);
    }
}

__global__ void __launch_bounds__(384) k_decode(const float* __restrict__ pred) {
    const int nT = 600;
    const int b  = blockIdx.x / nT;
    const int t  = blockIdx.x % nT;
    const int a0 = t << 7;
    const int na = min(128, A_N - a0);
    const float4* src = (const float4*)(pred + ((size_t)b * A_N + a0) * 84);
    const int tid = threadIdx.x;

    if (na == 128) {                      // 2688 float4 = 7 * 384, no tail
        float4 v0 = src[tid];
        float4 v1 = src[tid + 384];
        float4 v2 = src[tid + 768];
        float4 v3 = src[tid + 1152];
        dec_process(v0, tid,        b, a0);
        dec_process(v1, tid + 384,  b, a0);
        dec_process(v2, tid + 768,  b, a0);
        dec_process(v3, tid + 1152, b, a0);
        float4 v4 = src[tid + 1536];
        float4 v5 = src[tid + 1920];
        float4 v6 = src[tid + 2304];
        dec_process(v4, tid + 1536, b, a0);
        dec_process(v5, tid + 1920, b, a0);
        dec_process(v6, tid + 2304, b, a0);
    } else {
        const int tot = na * 21;
        for (int i = tid; i < tot; i += 384) dec_process(src[i], i, b, a0);
    }
}

// =====================================================================
// Kernel 2: per (b,c) exact top-256 + fused greedy NMS + top-100
// =====================================================================
__global__ void __launch_bounds__(256, 6) k_select(const float* __restrict__ pred,
                                                   const float* __restrict__ anchors) {
    extern __shared__ unsigned char sm[];
    unsigned*           hist = (unsigned*)sm;                      // 8KB
    unsigned*           csum = (unsigned*)(sm + 8192);             // 257 u32
    int*                ctrl = (int*)(sm + 9232);                  // 8 int
    unsigned long long* TIE  = (unsigned long long*)(sm + 9472);   // 32 u64
    unsigned long long* BUF  = (unsigned long long*)(sm + 9728);   // 8KB

    const int tid  = threadIdx.x;
    const int task = blockIdx.x;
    const int b    = task / NCLS;
    const int c    = task % NCLS;

    const int n = g_cnt[task * CNTSTR];
    bool fallback = !(n >= KPRE && n <= CCAP);
    const unsigned long long* cand = g_cand + (size_t)task * CCAP;

    for (int i = tid; i < NBIN2; i += 256) hist[i] = 0;
    if (tid < 8) ctrl[tid] = 0;
    __syncthreads();

    if (!fallback) {
        for (int i = tid; i < n; i += 256) {
            unsigned key = (unsigned)(cand[i] >> 32);
            unsigned bin = (key - SEL_BASE) >> 10; if (bin > 2047u) bin = 2047u;
            atomicAdd(&hist[bin], 1u);
        }
        __syncthreads();
        unsigned s8 = 0;
        {
            const int base = tid * 8;
#pragma unroll
            for (int r = 0; r < 8; ++r) s8 += hist[base + r];
        }
        unsigned incl = suffix_scan(s8, tid, csum);
        crossing2(hist, incl - s8, ctrl, KPRE, tid);
        const unsigned B1 = (unsigned)ctrl[0];
        const unsigned C1 = (unsigned)ctrl[1];
        const unsigned tie = hist[B1];
        __syncthreads();

        if (tie <= 32u) {
            if (tid == 0) { ctrl[2] = 0; ctrl[3] = 0; }
            __syncthreads();
            for (int i = tid; i < n; i += 256) {
                unsigned long long e = cand[i];
                unsigned key = (unsigned)(e >> 32);
                unsigned bin = (key - SEL_BASE) >> 10; if (bin > 2047u) bin = 2047u;
                if (bin > B1) {
                    int p = atomicAdd(&ctrl[2], 1);
                    BUF[p] = e;
                } else if (bin == B1) {
                    int q = atomicAdd(&ctrl[3], 1);
                    TIE[q] = e;
                }
            }
            __syncthreads();
            if (tid < 32) {
                const int t2 = ctrl[3];
                unsigned long long v = (tid < t2) ? TIE[tid] : 0ull;
#pragma unroll
                for (int k = 2; k <= 32; k <<= 1) {
#pragma unroll
                    for (int j = k >> 1; j > 0; j >>= 1) {
                        unsigned long long o = __shfl_xor_sync(0xFFFFFFFFu, v, j);
                        bool dir   = ((tid & k) == 0);
                        bool lower = ((tid & j) == 0);
                        bool keepMin = (lower == dir);
                        unsigned long long mn = v < o ? v : o;
                        unsigned long long mx = v < o ? o : v;
                        v = keepMin ? mn : mx;
                    }
                }
                int rankDesc = 31 - tid;
                int needTie = KPRE - (int)C1;
                if (rankDesc < needTie) BUF[C1 + rankDesc] = v;
            }
            __syncthreads();
            if (tid == 0) ctrl[2] = KPRE;
            __syncthreads();
        } else {
            const unsigned need = C1 + tie;
            if (need <= (unsigned)BUFN) {
                const unsigned minKey = SEL_BASE + (B1 << 10);
                if (tid == 0) ctrl[2] = 0;
                __syncthreads();
                for (int i = tid; i < n; i += 256) {
                    unsigned long long e = cand[i];
                    if ((unsigned)(e >> 32) >= minKey) {
                        int p = atomicAdd(&ctrl[2], 1);
                        BUF[p] = e;
                    }
                }
                __syncthreads();
            } else {
                fallback = true;
            }
        }
    }

    if (fallback) {
        for (int i = tid; i < NBIN2; i += 256) hist[i] = 0;
        if (tid < 8) ctrl[tid] = 0;
        __syncthreads();
        unsigned cnt = 0;
        for (int a = tid; a < A_N; a += 256) {
            float x = pred[((size_t)b * A_N + a) * 84 + 4 + c];
            float s = 1.0f / (1.0f + expf(-x));
            if (s > 0.05f) { ++cnt; atomicAdd(&hist[fkey32(s) >> 21], 1u); }
        }
        for (int o = 16; o; o >>= 1) cnt += __shfl_down_sync(0xFFFFFFFFu, cnt, o);
        if ((tid & 31) == 0) atomicAdd((unsigned*)&ctrl[5], cnt);
        __syncthreads();
        const unsigned total = (unsigned)ctrl[5];
        if (total == 0u) {
            for (int p = tid; p < MDPC; p += 256) {
                g_cls_scores[task * MDPC + p] = -1.0f;
                g_cls_boxes [task * MDPC + p] = make_float4(0.f, 0.f, 0.f, 0.f);
            }
            if (tid == 0) g_cnt[task * CNTSTR] = 0;
            return;
        }
        const unsigned target = total < (unsigned)KPRE ? total : (unsigned)KPRE;
        (void)suffix_total<8>(hist, csum, tid);
        crossing<8>(hist, csum, ctrl, target, tid);
        const unsigned B1 = (unsigned)ctrl[0];
        const unsigned C1 = (unsigned)ctrl[1];
        __syncthreads();
        for (int i = tid; i < NBIN2; i += 256) hist[i] = 0;
        __syncthreads();
        for (int a = tid; a < A_N; a += 256) {
            float x = pred[((size_t)b * A_N + a) * 84 + 4 + c];
            float s = 1.0f / (1.0f + expf(-x));
            if (s > 0.05f) {
                unsigned key = fkey32(s);
                if ((key >> 21) == B1) atomicAdd(&hist[(key >> 10) & 0x7FFu], 1u);
            }
        }
        __syncthreads();
        (void)suffix_total<8>(hist, csum, tid);
        crossing<8>(hist, csum, ctrl, target - C1, tid);
        const unsigned B2 = (unsigned)ctrl[0];
        if (tid == 0) ctrl[2] = 0;
        __syncthreads();
        for (int a = tid; a < A_N; a += 256) {
            float x = pred[((size_t)b * A_N + a) * 84 + 4 + c];
            float s = 1.0f / (1.0f + expf(-x));
            if (s > 0.05f) {
                unsigned key = fkey32(s);
                unsigned l1 = key >> 21;
                bool take = l1 > B1 || (l1 == B1 && ((key >> 10) & 0x7FFu) >= B2);
                if (take) {
                    int p = atomicAdd(&ctrl[2], 1);
                    if (p < BUFN)
                        BUF[p] = ((unsigned long long)key << 32) | (unsigned)(~(unsigned)a);
                }
            }
        }
        __syncthreads();
    }

    if (tid == 0) g_cnt[task * CNTSTR] = 0;      // reset for next graph replay

    int sel = ctrl[2]; if (sel > BUFN) sel = BUFN;
    const int W = (sel <= 256) ? 256 : ((sel <= 512) ? 512 : 1024);
    for (int i = sel + tid; i < W; i += 256) BUF[i] = 0ull;
    __syncthreads();

    for (int kk = 2; kk <= W; kk <<= 1) {
        for (int j = kk >> 1; j > 0; j >>= 1) {
            for (int i = tid; i < W; i += 256) {
                int ix = i ^ j;
                if (ix > i) {
                    unsigned long long x = BUF[i], y = BUF[ix];
                    bool sw = ((i & kk) == 0) ? (x < y) : (x > y);
                    if (sw) { BUF[i] = y; BUF[ix] = x; }
                }
            }
            __syncthreads();
        }
    }

    // ---- fused greedy NMS on top-256 ----
    float4* BXS   = (float4*)sm;                 // [256] = 4KB
    float*  AR    = (float*)(sm + 4096);
    float*  SC    = (float*)(sm + 5120);
    int*    KEEPF = (int*)(sm + 6144);           // [256]

    float ax1, ay1, ax2, ay2, aa;
    bool alive;
    {
        unsigned long long e = BUF[tid];
        unsigned key  = (unsigned)(e >> 32);
        unsigned aidx = ~(unsigned)(e & 0xFFFFFFFFull);
        float  s  = -1.0f;
        float4 bx = make_float4(0.f, 0.f, 0.f, 0.f);
        if (key) {
            const float4 bp = *(const float4*)(pred + ((size_t)b * A_N + aidx) * 84);
            const float4 an = ((const float4*)anchors)[aidx];
            float cx = bp.x * 0.1f * an.z + an.x;
            float cy = bp.y * 0.1f * an.w + an.y;
            float w  = expf(bp.z * 0.2f) * an.z;
            float h  = expf(bp.w * 0.2f) * an.w;
            bx = make_float4(cx - w * 0.5f, cy - h * 0.5f, cx + w * 0.5f, cy + h * 0.5f);
            s  = __uint_as_float(key & 0x7FFFFFFFu);
        }
        BXS[tid] = bx;
        ax1 = bx.x; ay1 = bx.y; ax2 = bx.z; ay2 = bx.w;
        aa  = (bx.z - bx.x) * (bx.w - bx.y);
        AR[tid] = aa;
        SC[tid] = s;
        alive = (key != 0u);
        KEEPF[tid] = alive ? 1 : 0;
    }
    __syncthreads();

    // greedy: for each kept i (ascending), all threads test pair (i, tid)
    int myrank = -1;
    int kcnt = 0;
    for (int i = 0; i < 256 && kcnt < MDPC; ++i) {
        if (KEEPF[i]) {
            if (i == tid) myrank = kcnt;
            ++kcnt;
            float4 bi = BXS[i];                  // broadcast
            float ai  = AR[i];
            if (tid > i && alive) {
                float iw = fmaxf(fminf(ax2, bi.z) - fmaxf(ax1, bi.x), 0.f);
                float ih = fmaxf(fminf(ay2, bi.w) - fmaxf(ay1, bi.y), 0.f);
                float inter = iw * ih;
                float u = aa + ai - inter;
                if (inter + inter > u && inter > 5e-9f) {
                    alive = false;
                    KEEPF[tid] = 0;
                }
            }
            __syncthreads();
        }
    }

    {
        if (myrank >= 0 && myrank < MDPC) {
            g_cls_scores[task * MDPC + myrank] = SC[tid];
            g_cls_boxes [task * MDPC + myrank] = BXS[tid];
        }
        for (int q = kcnt + tid; q < MDPC; q += 256) {
            g_cls_scores[task * MDPC + q] = -1.0f;
            g_cls_boxes [task * MDPC + q] = make_float4(0.f, 0.f, 0.f, 0.f);
        }
    }
}

// =====================================================================
// Kernel 3: per image top-100 of 8000
// =====================================================================
__global__ void __launch_bounds__(256) k_final(float* __restrict__ out) {
    __shared__ unsigned hist[NBINF];
    __shared__ unsigned long long BUF[256];
    __shared__ unsigned csum[257];
    __shared__ int ctrl[8];
    __shared__ int vc;

    const int tid = threadIdx.x;
    const int b   = blockIdx.x;
    const float* sc = g_cls_scores + b * NCLS * MDPC;

    for (int i = tid; i < NBINF; i += 256) hist[i] = 0;
    if (tid < 8) ctrl[tid] = 0;
    __syncthreads();

    unsigned cnt = 0;
    for (int i = tid; i < NCLS * MDPC; i += 256) {
        float s = sc[i];
        if (s > 0.0f) { ++cnt; atomicAdd(&hist[(fkey32(s) - FIN_BASE) >> 14], 1u); }
    }
    for (int o = 16; o; o >>= 1) cnt += __shfl_down_sync(0xFFFFFFFFu, cnt, o);
    if ((tid & 31) == 0) atomicAdd((unsigned*)&ctrl[5], cnt);
    __syncthreads();
    const unsigned npos = (unsigned)ctrl[5];

    if (npos >= (unsigned)MAXD) {
        (void)suffix_total<16>(hist, csum, tid);
        crossing<16>(hist, csum, ctrl, MAXD, tid);
        const unsigned B1 = (unsigned)ctrl[0];
        const unsigned C1 = (unsigned)ctrl[1];
        __syncthreads();
        for (int i = tid; i < NBINF; i += 256) hist[i] = 0;
        __syncthreads();
        for (int i = tid; i < NCLS * MDPC; i += 256) {
            float s = sc[i];
            if (s > 0.0f) {
                unsigned key = fkey32(s);
                if (((key - FIN_BASE) >> 14) == B1) atomicAdd(&hist[(key >> 2) & 0xFFFu], 1u);
            }
        }
        __syncthreads();
        (void)suffix_total<16>(hist, csum, tid);
        crossing<16>(hist, csum, ctrl, MAXD - C1, tid);
        const unsigned B2 = (unsigned)ctrl[0];
        if (tid == 0) ctrl[2] = 0;
        __syncthreads();
        for (int i = tid; i < NCLS * MDPC; i += 256) {
            float s = sc[i];
            if (s > 0.0f) {
                unsigned key = fkey32(s);
                unsigned l1 = (key - FIN_BASE) >> 14;
                bool take = l1 > B1 || (l1 == B1 && ((key >> 2) & 0xFFFu) >= B2);
                if (take) {
                    int p = atomicAdd(&ctrl[2], 1);
                    if (p < 256)
                        BUF[p] = ((unsigned long long)key << 32) | (unsigned)(~(unsigned)i);
                }
            }
        }
        __syncthreads();
    } else {
        if (tid == 0) ctrl[2] = 0;
        __syncthreads();
        for (int i = tid; i < NCLS * MDPC; i += 256) {
            float s = sc[i];
            if (s > 0.0f) {
                int p = atomicAdd(&ctrl[2], 1);
                if (p < 256)
                    BUF[p] = ((unsigned long long)fkey32(s) << 32) | (unsigned)(~(unsigned)i);
            }
        }
        __syncthreads();
    }

    int sel = ctrl[2]; if (sel > 256) sel = 256;
    if (tid >= sel) BUF[tid] = 0ull;
    __syncthreads();

    for (int kk = 2; kk <= 256; kk <<= 1) {
        for (int j = kk >> 1; j > 0; j >>= 1) {
            int ix = tid ^ j;
            if (ix > tid) {
                unsigned long long x = BUF[tid], y = BUF[ix];
                bool sw = ((tid & kk) == 0) ? (x < y) : (x > y);
                if (sw) { BUF[tid] = y; BUF[ix] = x; }
            }
            __syncthreads();
        }
    }

    if (tid == 0) vc = 0;
    __syncthreads();

    if (tid < MAXD) {
        unsigned long long e = BUF[tid];
        unsigned key  = (unsigned)(e >> 32);
        unsigned flat = ~(unsigned)(e & 0xFFFFFFFFull);
        bool valid = (key != 0u);
        float4 bx = make_float4(0.f, 0.f, 0.f, 0.f);
        float cls = 0.0f, so = 0.0f;
        if (valid) {
            float s = __uint_as_float((key & 0x80000000u) ? (key & 0x7FFFFFFFu) : ~key);
            bx  = g_cls_boxes[b * NCLS * MDPC + flat];
            cls = (float)(flat / MDPC);
            so  = s;
            atomicAdd(&vc, 1);
        }
        out[b * 400 + tid * 4 + 0] = bx.x;
        out[b * 400 + tid * 4 + 1] = bx.y;
        out[b * 400 + tid * 4 + 2] = bx.z;
        out[b * 400 + tid * 4 + 3] = bx.w;
        out[NB * MAXD * 4 + b * MAXD + tid]             = so;
        out[NB * MAXD * 4 + NB * MAXD + b * MAXD + tid] = cls;
    }
    __syncthreads();
    if (tid == 0) out[NB * MAXD * 6 + b] = (float)vc;
}

// =====================================================================
extern "C" void kernel_launch(void* const* d_in, const int* in_sizes, int n_in,
                              void* d_out, int out_size) {
    (void)in_sizes; (void)n_in; (void)out_size;
    const float* pred    = (const float*)d_in[1];
    const float* anchors = (const float*)d_in[2];
    float* out = (float*)d_out;

    k_decode<<<NB * 600, 384>>>(pred);

    cudaFuncSetAttribute(k_select, cudaFuncAttributeMaxDynamicSharedMemorySize, 17920);
    k_select<<<NTASK, 256, 17920>>>(pred, anchors);

    k_final<<<NB, 256>>>(out);
}